// round 2
// baseline (speedup 1.0000x reference)
#include <cuda_runtime.h>
#include <math.h>
#include <float.h>

#define BB 16
#define TT 512
#define DD 512

// ---------------- scratch (static __device__ — no allocations) ----------------
__device__ float g_A[512 * 512];                    // DFT matrix, rows r=2(k-1)+comp, 510 used
__device__ float g_X[(size_t)BB * 512 * DD];        // DFT output [b][row][d]
__device__ float g_xT[(size_t)BB * DD * TT];        // x transposed to [b][d][t]
__device__ int   g_tk [BB * DD * 4];                // top-4 freq indices per (b,d)
__device__ float g_tXr[BB * DD * 4];                // top-4 Re(X)
__device__ float g_tXi[BB * DD * 4];                // top-4 Im(X)
__device__ float g_xtr[BB * DD];                    // x_trans (before +b_lin)
__device__ float g_ctab[512];                       // cos(2*pi*j/512)
__device__ float g_stab[512];                       // sin(2*pi*j/512)

// ---------------- init: DFT matrix + trig tables ----------------
__global__ void k_init() {
    int r = blockIdx.x;          // 0..511
    int t = threadIdx.x;         // 0..511
    float val = 0.f;
    if (r < 510) {
        int k = (r >> 1) + 1;                    // 1..255
        int idx = (k * t) & 511;
        float s, c;
        sincospif((float)idx * (1.0f / 256.0f), &s, &c);  // angle 2*pi*idx/512
        val = (r & 1) ? -s : c;                  // Xr row: cos, Xi row: -sin
        if (r == 0) g_ctab[t] = c;               // k=1 -> idx = t
        if (r == 1) g_stab[t] = s;
    }
    g_A[r * 512 + t] = val;
}

// ---------------- transpose x (B,T,D) -> (B,D,T) ----------------
__global__ void k_transpose(const float* __restrict__ x) {
    __shared__ float tile[32][33];
    int b  = blockIdx.z;
    int d0 = blockIdx.x * 32;
    int t0 = blockIdx.y * 32;
    int tx = threadIdx.x, ty = threadIdx.y;
    const float* xb = x + (size_t)b * TT * DD;
    #pragma unroll
    for (int i = ty; i < 32; i += 8)
        tile[i][tx] = xb[(size_t)(t0 + i) * DD + d0 + tx];
    __syncthreads();
    float* ob = g_xT + (size_t)b * DD * TT;
    #pragma unroll
    for (int i = ty; i < 32; i += 8)
        ob[(size_t)(d0 + i) * TT + t0 + tx] = tile[tx][i];
}

// ---------------- DFT as SGEMM: g_X[b] = g_A (510x512) * x[b] (512x512) ----------------
__global__ void __launch_bounds__(256) k_dft(const float* __restrict__ x) {
    __shared__ float As[16][65];
    __shared__ float Bs[16][68];
    int b = blockIdx.z;
    int rowBase = blockIdx.y * 64;
    int colBase = blockIdx.x * 64;
    int tid = threadIdx.x;
    int tx = tid & 15, ty = tid >> 4;
    float acc[4][4];
    #pragma unroll
    for (int i = 0; i < 4; i++)
        #pragma unroll
        for (int j = 0; j < 4; j++) acc[i][j] = 0.f;

    const float* xb = x + (size_t)b * TT * DD;
    const float* Ap = g_A + (size_t)(rowBase + (tid >> 2)) * 512 + ((tid & 3) << 2);
    int aR = tid >> 2;            // 0..63
    int aT = (tid & 3) << 2;      // 0,4,8,12
    int bT = tid >> 4;            // 0..15
    int bD = (tid & 15) << 2;     // 0..60

    for (int t0 = 0; t0 < 512; t0 += 16) {
        float4 av = *(const float4*)(Ap + t0);
        As[aT + 0][aR] = av.x; As[aT + 1][aR] = av.y;
        As[aT + 2][aR] = av.z; As[aT + 3][aR] = av.w;
        float4 bv = *(const float4*)(xb + (size_t)(t0 + bT) * DD + colBase + bD);
        *(float4*)(&Bs[bT][bD]) = bv;
        __syncthreads();
        #pragma unroll
        for (int kk = 0; kk < 16; kk++) {
            float a0 = As[kk][ty * 4 + 0], a1 = As[kk][ty * 4 + 1];
            float a2 = As[kk][ty * 4 + 2], a3 = As[kk][ty * 4 + 3];
            float b0 = Bs[kk][tx * 4 + 0], b1 = Bs[kk][tx * 4 + 1];
            float b2 = Bs[kk][tx * 4 + 2], b3 = Bs[kk][tx * 4 + 3];
            acc[0][0] = fmaf(a0, b0, acc[0][0]); acc[0][1] = fmaf(a0, b1, acc[0][1]);
            acc[0][2] = fmaf(a0, b2, acc[0][2]); acc[0][3] = fmaf(a0, b3, acc[0][3]);
            acc[1][0] = fmaf(a1, b0, acc[1][0]); acc[1][1] = fmaf(a1, b1, acc[1][1]);
            acc[1][2] = fmaf(a1, b2, acc[1][2]); acc[1][3] = fmaf(a1, b3, acc[1][3]);
            acc[2][0] = fmaf(a2, b0, acc[2][0]); acc[2][1] = fmaf(a2, b1, acc[2][1]);
            acc[2][2] = fmaf(a2, b2, acc[2][2]); acc[2][3] = fmaf(a2, b3, acc[2][3]);
            acc[3][0] = fmaf(a3, b0, acc[3][0]); acc[3][1] = fmaf(a3, b1, acc[3][1]);
            acc[3][2] = fmaf(a3, b2, acc[3][2]); acc[3][3] = fmaf(a3, b3, acc[3][3]);
        }
        __syncthreads();
    }
    #pragma unroll
    for (int i = 0; i < 4; i++) {
        int r = rowBase + ty * 4 + i;
        if (r < 510) {
            float4 v = make_float4(acc[i][0], acc[i][1], acc[i][2], acc[i][3]);
            *(float4*)(g_X + ((size_t)b * 512 + r) * 512 + colBase + tx * 4) = v;
        }
    }
}

// ---------------- top-4 amplitudes per (b,d) ----------------
__global__ void k_topk() {
    int gid = blockIdx.x * blockDim.x + threadIdx.x;
    if (gid >= BB * DD) return;
    int b = gid >> 9, d = gid & 511;
    const float* Xb = g_X + (size_t)b * 512 * 512 + d;
    float bA0 = -1.f, bA1 = -1.f, bA2 = -1.f, bA3 = -1.f;
    int   bK0 = 0, bK1 = 0, bK2 = 0, bK3 = 0;
    float bR0 = 0, bR1 = 0, bR2 = 0, bR3 = 0;
    float bI0 = 0, bI1 = 0, bI2 = 0, bI3 = 0;
    for (int k = 1; k <= 255; k++) {
        float xr = Xb[(size_t)(2 * k - 2) * 512];
        float xi = Xb[(size_t)(2 * k - 1) * 512];
        float a = xr * xr + xi * xi;
        if (a > bA3) {
            if (a > bA0) {
                bA3 = bA2; bK3 = bK2; bR3 = bR2; bI3 = bI2;
                bA2 = bA1; bK2 = bK1; bR2 = bR1; bI2 = bI1;
                bA1 = bA0; bK1 = bK0; bR1 = bR0; bI1 = bI0;
                bA0 = a; bK0 = k; bR0 = xr; bI0 = xi;
            } else if (a > bA1) {
                bA3 = bA2; bK3 = bK2; bR3 = bR2; bI3 = bI2;
                bA2 = bA1; bK2 = bK1; bR2 = bR1; bI2 = bI1;
                bA1 = a; bK1 = k; bR1 = xr; bI1 = xi;
            } else if (a > bA2) {
                bA3 = bA2; bK3 = bK2; bR3 = bR2; bI3 = bI2;
                bA2 = a; bK2 = k; bR2 = xr; bI2 = xi;
            } else {
                bA3 = a; bK3 = k; bR3 = xr; bI3 = xi;
            }
        }
    }
    g_tk [gid * 4 + 0] = bK0; g_tk [gid * 4 + 1] = bK1;
    g_tk [gid * 4 + 2] = bK2; g_tk [gid * 4 + 3] = bK3;
    g_tXr[gid * 4 + 0] = bR0; g_tXr[gid * 4 + 1] = bR1;
    g_tXr[gid * 4 + 2] = bR2; g_tXr[gid * 4 + 3] = bR3;
    g_tXi[gid * 4 + 0] = bI0; g_tXi[gid * 4 + 1] = bI1;
    g_tXi[gid * 4 + 2] = bI2; g_tXi[gid * 4 + 3] = bI3;
}

// ---------------- fused per-series: season, rem, cumsum, moving avgs, trend, W_lin reduce ----------------
__global__ void __launch_bounds__(256) k_series(const float* __restrict__ W_trend,
                                                const float* __restrict__ b_trend,
                                                const float* __restrict__ W_lin) {
    __shared__ float s_x[512];
    __shared__ float s_rem[512];
    __shared__ float s_cs[513];
    __shared__ float s_cos[512];
    __shared__ float s_sin[512];
    __shared__ float s_red[8];
    __shared__ int   sk[4];
    __shared__ float sxr[4], sxi[4];

    int gid = blockIdx.x;            // b*512 + d
    int tid = threadIdx.x;

    s_cos[tid] = g_ctab[tid]; s_cos[tid + 256] = g_ctab[tid + 256];
    s_sin[tid] = g_stab[tid]; s_sin[tid + 256] = g_stab[tid + 256];
    const float* xs = g_xT + (size_t)gid * TT;
    s_x[tid] = xs[tid]; s_x[tid + 256] = xs[tid + 256];
    if (tid < 4) {
        sk [tid] = g_tk [gid * 4 + tid];
        sxr[tid] = g_tXr[gid * 4 + tid];
        sxi[tid] = g_tXi[gid * 4 + tid];
    }
    __syncthreads();

    // season + remainder. season = (2/T) * Re(X * e^{+i 2 pi k t / T})
    #pragma unroll
    for (int tt = 0; tt < 2; tt++) {
        int t = tid + tt * 256;
        float se = 0.f;
        #pragma unroll
        for (int j = 0; j < 4; j++) {
            int idx = (sk[j] * t) & 511;
            se += sxr[j] * s_cos[idx] - sxi[j] * s_sin[idx];
        }
        se *= (2.0f / 512.0f);
        s_rem[t] = s_x[t] - se;
    }
    __syncthreads();

    // exclusive cumsum of rem into s_cs[0..512], warp 0 only
    if (tid < 32) {
        int base = tid * 16;
        float run = 0.f, pref[16];
        #pragma unroll
        for (int i = 0; i < 16; i++) { pref[i] = run; run += s_rem[base + i]; }
        float inc = run;
        #pragma unroll
        for (int sft = 1; sft < 32; sft <<= 1) {
            float v = __shfl_up_sync(0xffffffffu, inc, sft);
            if (tid >= sft) inc += v;
        }
        float excl = inc - run;
        #pragma unroll
        for (int i = 0; i < 16; i++) s_cs[base + i] = excl + pref[i];
        if (tid == 31) s_cs[512] = inc;
    }
    __syncthreads();

    float Wt[6], bt[6];
    #pragma unroll
    for (int j = 0; j < 6; j++) { Wt[j] = W_trend[j]; bt[j] = b_trend[j]; }
    const int   KSv[6] = {4, 8, 12, 16, 24, 32};
    const float inv[6] = {0.25f, 0.125f, 1.f / 12.f, 0.0625f, 1.f / 24.f, 0.03125f};
    float rem0 = s_rem[0], remL = s_rem[511];
    float acc = 0.f;

    #pragma unroll
    for (int tt = 0; tt < 2; tt++) {
        int t = tid + tt * 256;
        float rem = s_rem[t];
        float mm[6], lg[6];
        float mx = -FLT_MAX;
        #pragma unroll
        for (int j = 0; j < 6; j++) {
            int k = KSv[j];
            int front = k >> 1, end = (k >> 1) - 1;   // all KS even
            int lo = t - front, hi = t + end;
            int clo = lo < 0 ? 0 : lo;
            int chi = hi > 511 ? 511 : hi;
            float ssum = s_cs[chi + 1] - s_cs[clo];
            if (lo < 0)   ssum += (float)(-lo) * rem0;
            if (hi > 511) ssum += (float)(hi - 511) * remL;
            mm[j] = ssum * inv[j];
            float l = fmaf(rem, Wt[j], bt[j]);
            lg[j] = l;
            mx = fmaxf(mx, l);
        }
        float es = 0.f, ws = 0.f;
        #pragma unroll
        for (int j = 0; j < 6; j++) {
            float e = expf(lg[j] - mx);
            es += e;
            ws = fmaf(e, mm[j], ws);
        }
        float trend = ws / es;
        float xsum = 2.0f * s_x[t] - rem + trend;   // x + season + trend
        acc = fmaf(xsum, W_lin[t], acc);
    }

    #pragma unroll
    for (int o = 16; o > 0; o >>= 1) acc += __shfl_down_sync(0xffffffffu, acc, o);
    if ((tid & 31) == 0) s_red[tid >> 5] = acc;
    __syncthreads();
    if (tid == 0) {
        float s = 0.f;
        #pragma unroll
        for (int w = 0; w < 8; w++) s += s_red[w];
        g_xtr[gid] = s;
    }
}

// ---------------- final routing: (B,D)->(B,8), softplus noise, softmax, top-4 ----------------
__global__ void k_router(const float* __restrict__ noise, const float* __restrict__ W_r,
                         const float* __restrict__ b_r, const float* __restrict__ W_noise,
                         const float* __restrict__ b_noise, const float* __restrict__ b_lin,
                         float* __restrict__ out) {
    int b = blockIdx.x;
    int tid = threadIdx.x;
    int m = tid & 7, c = tid >> 3;   // c: 0..31 chunks of 16 d
    __shared__ float sp[256], sn[256];
    __shared__ float slog[8];
    const float* xt = g_xtr + b * DD;
    float blin = b_lin[0];
    float p = 0.f, pn = 0.f;
    #pragma unroll
    for (int i = 0; i < 16; i++) {
        int d = c * 16 + i;
        float v = xt[d] + blin;
        p  = fmaf(v, W_r[d * 8 + m], p);
        pn = fmaf(v, W_noise[d * 8 + m], pn);
    }
    sp[tid] = p; sn[tid] = pn;
    __syncthreads();
    if (tid < 8) {
        float P = 0.f, N = 0.f;
        for (int cc = 0; cc < 32; cc++) { P += sp[cc * 8 + tid]; N += sn[cc * 8 + tid]; }
        float base = P + b_r[tid];
        float nl = N + b_noise[tid];
        float ns = log1pf(expf(-fabsf(nl))) + fmaxf(nl, 0.f);   // softplus
        slog[tid] = base + noise[b * 8 + tid] * ns;
    }
    __syncthreads();
    if (tid == 0) {
        float lg[8], mx = -FLT_MAX;
        #pragma unroll
        for (int i = 0; i < 8; i++) { lg[i] = slog[i]; mx = fmaxf(mx, lg[i]); }
        float es = 0.f, pw[8];
        #pragma unroll
        for (int i = 0; i < 8; i++) { pw[i] = expf(lg[i] - mx); es += pw[i]; }
        #pragma unroll
        for (int i = 0; i < 8; i++) pw[i] /= es;
        #pragma unroll
        for (int i = 0; i < 8; i++) {
            int rank = 0;
            #pragma unroll
            for (int j = 0; j < 8; j++)
                if (pw[j] > pw[i] || (pw[j] == pw[i] && j < i)) rank++;
            out[b * 8 + i] = (rank < 4) ? pw[i] : 0.f;
        }
    }
}

// ---------------- launch ----------------
extern "C" void kernel_launch(void* const* d_in, const int* in_sizes, int n_in,
                              void* d_out, int out_size) {
    const float* x       = (const float*)d_in[0];
    const float* noise   = (const float*)d_in[1];
    const float* W_r     = (const float*)d_in[2];
    const float* b_r     = (const float*)d_in[3];
    const float* W_noise = (const float*)d_in[4];
    const float* b_noise = (const float*)d_in[5];
    const float* W_trend = (const float*)d_in[6];
    const float* b_trend = (const float*)d_in[7];
    const float* W_lin   = (const float*)d_in[8];
    const float* b_lin   = (const float*)d_in[9];
    float* out = (float*)d_out;

    k_init<<<512, 512>>>();
    k_transpose<<<dim3(16, 16, 16), dim3(32, 8)>>>(x);
    k_dft<<<dim3(8, 8, 16), 256>>>(x);
    k_topk<<<32, 256>>>();
    k_series<<<BB * DD, 256>>>(W_trend, b_trend, W_lin);
    k_router<<<16, 256>>>(noise, W_r, b_r, W_noise, b_noise, b_lin, out);
}

// round 3
// speedup vs baseline: 1.3124x; 1.3124x over previous
#include <cuda_runtime.h>
#include <math.h>
#include <float.h>

#define BB 16
#define TT 512
#define DD 512

// ---------------- scratch (static __device__ — no allocations) ----------------
__device__ float g_A[512 * 512];                    // DFT matrix, rows r=2(k-1)+comp, 510 used
__device__ float g_X[(size_t)BB * 512 * DD];        // DFT output [b][row][d]
__device__ float g_xT[(size_t)BB * DD * TT];        // x transposed to [b][d][t]
__device__ int   g_tk [BB * DD * 4];                // top-4 freq indices per (b,d)
__device__ float g_tXr[BB * DD * 4];                // top-4 Re(X)
__device__ float g_tXi[BB * DD * 4];                // top-4 Im(X)
__device__ float g_xtr[BB * DD];                    // x_trans (before +b_lin)
__device__ float g_ctab[512];                       // cos(2*pi*j/512)
__device__ float g_stab[512];                       // sin(2*pi*j/512)

// ---------------- init: DFT matrix + trig tables ----------------
__global__ void k_init() {
    int r = blockIdx.x;          // 0..511
    int t = threadIdx.x;         // 0..511
    float val = 0.f;
    if (r < 510) {
        int k = (r >> 1) + 1;                    // 1..255
        int idx = (k * t) & 511;
        float s, c;
        sincospif((float)idx * (1.0f / 256.0f), &s, &c);  // angle 2*pi*idx/512
        val = (r & 1) ? -s : c;                  // Xr row: cos, Xi row: -sin
        if (r == 0) g_ctab[t] = c;               // k=1 -> idx = t
        if (r == 1) g_stab[t] = s;
    }
    g_A[r * 512 + t] = val;
}

// ---------------- transpose x (B,T,D) -> (B,D,T) ----------------
__global__ void k_transpose(const float* __restrict__ x) {
    __shared__ float tile[32][33];
    int b  = blockIdx.z;
    int d0 = blockIdx.x * 32;
    int t0 = blockIdx.y * 32;
    int tx = threadIdx.x, ty = threadIdx.y;
    const float* xb = x + (size_t)b * TT * DD;
    #pragma unroll
    for (int i = ty; i < 32; i += 8)
        tile[i][tx] = xb[(size_t)(t0 + i) * DD + d0 + tx];
    __syncthreads();
    float* ob = g_xT + (size_t)b * DD * TT;
    #pragma unroll
    for (int i = ty; i < 32; i += 8)
        ob[(size_t)(d0 + i) * TT + t0 + tx] = tile[tx][i];
}

// ---------------- DFT as SGEMM: g_X[b] = g_A (510x512) * x[b] (512x512) ----------------
__global__ void __launch_bounds__(256) k_dft(const float* __restrict__ x) {
    __shared__ float As[16][65];
    __shared__ float Bs[16][68];
    int b = blockIdx.z;
    int rowBase = blockIdx.y * 64;
    int colBase = blockIdx.x * 64;
    int tid = threadIdx.x;
    int tx = tid & 15, ty = tid >> 4;
    float acc[4][4];
    #pragma unroll
    for (int i = 0; i < 4; i++)
        #pragma unroll
        for (int j = 0; j < 4; j++) acc[i][j] = 0.f;

    const float* xb = x + (size_t)b * TT * DD;
    const float* Ap = g_A + (size_t)(rowBase + (tid >> 2)) * 512 + ((tid & 3) << 2);
    int aR = tid >> 2;            // 0..63
    int aT = (tid & 3) << 2;      // 0,4,8,12
    int bT = tid >> 4;            // 0..15
    int bD = (tid & 15) << 2;     // 0..60

    for (int t0 = 0; t0 < 512; t0 += 16) {
        float4 av = *(const float4*)(Ap + t0);
        As[aT + 0][aR] = av.x; As[aT + 1][aR] = av.y;
        As[aT + 2][aR] = av.z; As[aT + 3][aR] = av.w;
        float4 bv = *(const float4*)(xb + (size_t)(t0 + bT) * DD + colBase + bD);
        *(float4*)(&Bs[bT][bD]) = bv;
        __syncthreads();
        #pragma unroll
        for (int kk = 0; kk < 16; kk++) {
            float a0 = As[kk][ty * 4 + 0], a1 = As[kk][ty * 4 + 1];
            float a2 = As[kk][ty * 4 + 2], a3 = As[kk][ty * 4 + 3];
            float b0 = Bs[kk][tx * 4 + 0], b1 = Bs[kk][tx * 4 + 1];
            float b2 = Bs[kk][tx * 4 + 2], b3 = Bs[kk][tx * 4 + 3];
            acc[0][0] = fmaf(a0, b0, acc[0][0]); acc[0][1] = fmaf(a0, b1, acc[0][1]);
            acc[0][2] = fmaf(a0, b2, acc[0][2]); acc[0][3] = fmaf(a0, b3, acc[0][3]);
            acc[1][0] = fmaf(a1, b0, acc[1][0]); acc[1][1] = fmaf(a1, b1, acc[1][1]);
            acc[1][2] = fmaf(a1, b2, acc[1][2]); acc[1][3] = fmaf(a1, b3, acc[1][3]);
            acc[2][0] = fmaf(a2, b0, acc[2][0]); acc[2][1] = fmaf(a2, b1, acc[2][1]);
            acc[2][2] = fmaf(a2, b2, acc[2][2]); acc[2][3] = fmaf(a2, b3, acc[2][3]);
            acc[3][0] = fmaf(a3, b0, acc[3][0]); acc[3][1] = fmaf(a3, b1, acc[3][1]);
            acc[3][2] = fmaf(a3, b2, acc[3][2]); acc[3][3] = fmaf(a3, b3, acc[3][3]);
        }
        __syncthreads();
    }
    #pragma unroll
    for (int i = 0; i < 4; i++) {
        int r = rowBase + ty * 4 + i;
        if (r < 510) {
            float4 v = make_float4(acc[i][0], acc[i][1], acc[i][2], acc[i][3]);
            *(float4*)(g_X + ((size_t)b * 512 + r) * 512 + colBase + tx * 4) = v;
        }
    }
}

// ---------------- top-4 amplitudes per (b,d): split freq axis across 8 warps ----------------
// block = 256 threads = 8 warps. Block owns 32 consecutive series (d fastest).
// Warp w scans freq chunk k in [w*32+1, w*32+32] (last chunk caps at 255).
// Lane l handles series gid = blockIdx.x*32 + l  -> loads coalesced across lanes.
__global__ void __launch_bounds__(256) k_topk() {
    __shared__ float sA[8][32][4];
    __shared__ int   sK[8][32][4];
    __shared__ float sR[8][32][4];
    __shared__ float sI[8][32][4];

    int lane = threadIdx.x & 31;
    int w    = threadIdx.x >> 5;             // 0..7 freq chunk
    int gid  = blockIdx.x * 32 + lane;       // series id
    int b = gid >> 9, d = gid & 511;
    const float* Xb = g_X + (size_t)b * 512 * 512 + d;

    float bA[4] = {-1.f, -1.f, -1.f, -1.f};
    int   bK[4] = {0x7fffffff, 0x7fffffff, 0x7fffffff, 0x7fffffff};
    float bR[4] = {0, 0, 0, 0};
    float bI[4] = {0, 0, 0, 0};

    int k0 = w * 32 + 1;
    int k1 = w * 32 + 32; if (k1 > 255) k1 = 255;
    for (int k = k0; k <= k1; k++) {
        float xr = Xb[(size_t)(2 * k - 2) * 512];
        float xi = Xb[(size_t)(2 * k - 1) * 512];
        float a = xr * xr + xi * xi;
        // strict > keeps earliest k within the chunk on ties
        if (a > bA[3]) {
            if (a > bA[0]) {
                bA[3]=bA[2]; bK[3]=bK[2]; bR[3]=bR[2]; bI[3]=bI[2];
                bA[2]=bA[1]; bK[2]=bK[1]; bR[2]=bR[1]; bI[2]=bI[1];
                bA[1]=bA[0]; bK[1]=bK[0]; bR[1]=bR[0]; bI[1]=bI[0];
                bA[0]=a; bK[0]=k; bR[0]=xr; bI[0]=xi;
            } else if (a > bA[1]) {
                bA[3]=bA[2]; bK[3]=bK[2]; bR[3]=bR[2]; bI[3]=bI[2];
                bA[2]=bA[1]; bK[2]=bK[1]; bR[2]=bR[1]; bI[2]=bI[1];
                bA[1]=a; bK[1]=k; bR[1]=xr; bI[1]=xi;
            } else if (a > bA[2]) {
                bA[3]=bA[2]; bK[3]=bK[2]; bR[3]=bR[2]; bI[3]=bI[2];
                bA[2]=a; bK[2]=k; bR[2]=xr; bI[2]=xi;
            } else {
                bA[3]=a; bK[3]=k; bR[3]=xr; bI[3]=xi;
            }
        }
    }
    #pragma unroll
    for (int j = 0; j < 4; j++) {
        sA[w][lane][j] = bA[j]; sK[w][lane][j] = bK[j];
        sR[w][lane][j] = bR[j]; sI[w][lane][j] = bI[j];
    }
    __syncthreads();

    // warp 0: lane l merges 32 candidates for series (blockIdx.x*32 + l)
    if (w == 0) {
        float mA[4] = {-1.f, -1.f, -1.f, -1.f};
        int   mK[4] = {0x7fffffff, 0x7fffffff, 0x7fffffff, 0x7fffffff};
        float mR[4] = {0, 0, 0, 0};
        float mI[4] = {0, 0, 0, 0};
        #pragma unroll
        for (int s = 0; s < 8; s++) {
            #pragma unroll
            for (int j = 0; j < 4; j++) {
                float a = sA[s][lane][j];
                int   k = sK[s][lane][j];
                float xr = sR[s][lane][j];
                float xi = sI[s][lane][j];
                // better(a,k ; A,K): amplitude desc, k asc tie-break
                bool b3 = (a > mA[3]) || (a == mA[3] && k < mK[3]);
                if (b3) {
                    bool b0 = (a > mA[0]) || (a == mA[0] && k < mK[0]);
                    bool b1 = (a > mA[1]) || (a == mA[1] && k < mK[1]);
                    bool b2 = (a > mA[2]) || (a == mA[2] && k < mK[2]);
                    if (b0) {
                        mA[3]=mA[2]; mK[3]=mK[2]; mR[3]=mR[2]; mI[3]=mI[2];
                        mA[2]=mA[1]; mK[2]=mK[1]; mR[2]=mR[1]; mI[2]=mI[1];
                        mA[1]=mA[0]; mK[1]=mK[0]; mR[1]=mR[0]; mI[1]=mI[0];
                        mA[0]=a; mK[0]=k; mR[0]=xr; mI[0]=xi;
                    } else if (b1) {
                        mA[3]=mA[2]; mK[3]=mK[2]; mR[3]=mR[2]; mI[3]=mI[2];
                        mA[2]=mA[1]; mK[2]=mK[1]; mR[2]=mR[1]; mI[2]=mI[1];
                        mA[1]=a; mK[1]=k; mR[1]=xr; mI[1]=xi;
                    } else if (b2) {
                        mA[3]=mA[2]; mK[3]=mK[2]; mR[3]=mR[2]; mI[3]=mI[2];
                        mA[2]=a; mK[2]=k; mR[2]=xr; mI[2]=xi;
                    } else {
                        mA[3]=a; mK[3]=k; mR[3]=xr; mI[3]=xi;
                    }
                }
            }
        }
        int og = blockIdx.x * 32 + lane;
        #pragma unroll
        for (int j = 0; j < 4; j++) {
            g_tk [og * 4 + j] = mK[j];
            g_tXr[og * 4 + j] = mR[j];
            g_tXi[og * 4 + j] = mI[j];
        }
    }
}

// ---------------- fused per-series: season, rem, cumsum, moving avgs, trend, W_lin reduce ----------------
__global__ void __launch_bounds__(256) k_series(const float* __restrict__ W_trend,
                                                const float* __restrict__ b_trend,
                                                const float* __restrict__ W_lin) {
    __shared__ float s_x[512];
    __shared__ float s_rem[512];
    __shared__ float s_cs[513];
    __shared__ float s_cos[512];
    __shared__ float s_sin[512];
    __shared__ float s_red[8];
    __shared__ int   sk[4];
    __shared__ float sxr[4], sxi[4];

    int gid = blockIdx.x;            // b*512 + d
    int tid = threadIdx.x;

    s_cos[tid] = g_ctab[tid]; s_cos[tid + 256] = g_ctab[tid + 256];
    s_sin[tid] = g_stab[tid]; s_sin[tid + 256] = g_stab[tid + 256];
    const float* xs = g_xT + (size_t)gid * TT;
    s_x[tid] = xs[tid]; s_x[tid + 256] = xs[tid + 256];
    if (tid < 4) {
        sk [tid] = g_tk [gid * 4 + tid];
        sxr[tid] = g_tXr[gid * 4 + tid];
        sxi[tid] = g_tXi[gid * 4 + tid];
    }
    __syncthreads();

    // season + remainder. season = (2/T) * Re(X * e^{+i 2 pi k t / T})
    #pragma unroll
    for (int tt = 0; tt < 2; tt++) {
        int t = tid + tt * 256;
        float se = 0.f;
        #pragma unroll
        for (int j = 0; j < 4; j++) {
            int idx = (sk[j] * t) & 511;
            se += sxr[j] * s_cos[idx] - sxi[j] * s_sin[idx];
        }
        se *= (2.0f / 512.0f);
        s_rem[t] = s_x[t] - se;
    }
    __syncthreads();

    // exclusive cumsum of rem into s_cs[0..512], warp 0 only
    if (tid < 32) {
        int base = tid * 16;
        float run = 0.f, pref[16];
        #pragma unroll
        for (int i = 0; i < 16; i++) { pref[i] = run; run += s_rem[base + i]; }
        float inc = run;
        #pragma unroll
        for (int sft = 1; sft < 32; sft <<= 1) {
            float v = __shfl_up_sync(0xffffffffu, inc, sft);
            if (tid >= sft) inc += v;
        }
        float excl = inc - run;
        #pragma unroll
        for (int i = 0; i < 16; i++) s_cs[base + i] = excl + pref[i];
        if (tid == 31) s_cs[512] = inc;
    }
    __syncthreads();

    float Wt[6], bt[6];
    #pragma unroll
    for (int j = 0; j < 6; j++) { Wt[j] = W_trend[j]; bt[j] = b_trend[j]; }
    const int   KSv[6] = {4, 8, 12, 16, 24, 32};
    const float inv[6] = {0.25f, 0.125f, 1.f / 12.f, 0.0625f, 1.f / 24.f, 0.03125f};
    float rem0 = s_rem[0], remL = s_rem[511];
    float acc = 0.f;

    #pragma unroll
    for (int tt = 0; tt < 2; tt++) {
        int t = tid + tt * 256;
        float rem = s_rem[t];
        float mm[6], lg[6];
        float mx = -FLT_MAX;
        #pragma unroll
        for (int j = 0; j < 6; j++) {
            int k = KSv[j];
            int front = k >> 1, end = (k >> 1) - 1;   // all KS even
            int lo = t - front, hi = t + end;
            int clo = lo < 0 ? 0 : lo;
            int chi = hi > 511 ? 511 : hi;
            float ssum = s_cs[chi + 1] - s_cs[clo];
            if (lo < 0)   ssum += (float)(-lo) * rem0;
            if (hi > 511) ssum += (float)(hi - 511) * remL;
            mm[j] = ssum * inv[j];
            float l = fmaf(rem, Wt[j], bt[j]);
            lg[j] = l;
            mx = fmaxf(mx, l);
        }
        float es = 0.f, ws = 0.f;
        #pragma unroll
        for (int j = 0; j < 6; j++) {
            float e = expf(lg[j] - mx);
            es += e;
            ws = fmaf(e, mm[j], ws);
        }
        float trend = ws / es;
        float xsum = 2.0f * s_x[t] - rem + trend;   // x + season + trend
        acc = fmaf(xsum, W_lin[t], acc);
    }

    #pragma unroll
    for (int o = 16; o > 0; o >>= 1) acc += __shfl_down_sync(0xffffffffu, acc, o);
    if ((tid & 31) == 0) s_red[tid >> 5] = acc;
    __syncthreads();
    if (tid == 0) {
        float s = 0.f;
        #pragma unroll
        for (int w = 0; w < 8; w++) s += s_red[w];
        g_xtr[gid] = s;
    }
}

// ---------------- final routing: (B,D)->(B,8), softplus noise, softmax, top-4 ----------------
__global__ void k_router(const float* __restrict__ noise, const float* __restrict__ W_r,
                         const float* __restrict__ b_r, const float* __restrict__ W_noise,
                         const float* __restrict__ b_noise, const float* __restrict__ b_lin,
                         float* __restrict__ out) {
    int b = blockIdx.x;
    int tid = threadIdx.x;
    int m = tid & 7, c = tid >> 3;   // c: 0..31 chunks of 16 d
    __shared__ float sp[256], sn[256];
    __shared__ float slog[8];
    const float* xt = g_xtr + b * DD;
    float blin = b_lin[0];
    float p = 0.f, pn = 0.f;
    #pragma unroll
    for (int i = 0; i < 16; i++) {
        int d = c * 16 + i;
        float v = xt[d] + blin;
        p  = fmaf(v, W_r[d * 8 + m], p);
        pn = fmaf(v, W_noise[d * 8 + m], pn);
    }
    sp[tid] = p; sn[tid] = pn;
    __syncthreads();
    if (tid < 8) {
        float P = 0.f, N = 0.f;
        for (int cc = 0; cc < 32; cc++) { P += sp[cc * 8 + tid]; N += sn[cc * 8 + tid]; }
        float base = P + b_r[tid];
        float nl = N + b_noise[tid];
        float ns = log1pf(expf(-fabsf(nl))) + fmaxf(nl, 0.f);   // softplus
        slog[tid] = base + noise[b * 8 + tid] * ns;
    }
    __syncthreads();
    if (tid == 0) {
        float lg[8], mx = -FLT_MAX;
        #pragma unroll
        for (int i = 0; i < 8; i++) { lg[i] = slog[i]; mx = fmaxf(mx, lg[i]); }
        float es = 0.f, pw[8];
        #pragma unroll
        for (int i = 0; i < 8; i++) { pw[i] = expf(lg[i] - mx); es += pw[i]; }
        #pragma unroll
        for (int i = 0; i < 8; i++) pw[i] /= es;
        #pragma unroll
        for (int i = 0; i < 8; i++) {
            int rank = 0;
            #pragma unroll
            for (int j = 0; j < 8; j++)
                if (pw[j] > pw[i] || (pw[j] == pw[i] && j < i)) rank++;
            out[b * 8 + i] = (rank < 4) ? pw[i] : 0.f;
        }
    }
}

// ---------------- launch ----------------
extern "C" void kernel_launch(void* const* d_in, const int* in_sizes, int n_in,
                              void* d_out, int out_size) {
    const float* x       = (const float*)d_in[0];
    const float* noise   = (const float*)d_in[1];
    const float* W_r     = (const float*)d_in[2];
    const float* b_r     = (const float*)d_in[3];
    const float* W_noise = (const float*)d_in[4];
    const float* b_noise = (const float*)d_in[5];
    const float* W_trend = (const float*)d_in[6];
    const float* b_trend = (const float*)d_in[7];
    const float* W_lin   = (const float*)d_in[8];
    const float* b_lin   = (const float*)d_in[9];
    float* out = (float*)d_out;

    k_init<<<512, 512>>>();
    k_transpose<<<dim3(16, 16, 16), dim3(32, 8)>>>(x);
    k_dft<<<dim3(8, 8, 16), 256>>>(x);
    k_topk<<<256, 256>>>();
    k_series<<<BB * DD, 256>>>(W_trend, b_trend, W_lin);
    k_router<<<16, 256>>>(noise, W_r, b_r, W_noise, b_noise, b_lin, out);
}

// round 4
// speedup vs baseline: 2.2752x; 1.7336x over previous
#include <cuda_runtime.h>
#include <math.h>
#include <float.h>

#define BB 16
#define TT 512
#define DD 512

// ---------------- scratch (static __device__ — no allocations) ----------------
__device__ float g_xT[(size_t)BB * DD * TT];        // x transposed to [b][d][t]
__device__ float g_xtr[BB * DD];                    // x_trans (before +b_lin)

// ---------------- transpose x (B,T,D) -> (B,D,T) ----------------
__global__ void k_transpose(const float* __restrict__ x) {
    __shared__ float tile[32][33];
    int b  = blockIdx.z;
    int d0 = blockIdx.x * 32;
    int t0 = blockIdx.y * 32;
    int tx = threadIdx.x, ty = threadIdx.y;
    const float* xb = x + (size_t)b * TT * DD;
    #pragma unroll
    for (int i = ty; i < 32; i += 8)
        tile[i][tx] = xb[(size_t)(t0 + i) * DD + d0 + tx];
    __syncthreads();
    float* ob = g_xT + (size_t)b * DD * TT;
    #pragma unroll
    for (int i = ty; i < 32; i += 8)
        ob[(size_t)(d0 + i) * TT + t0 + tx] = tile[tx][i];
}

// ---------------- fused per-series: FFT, top-4, season, trend, W_lin reduce ----------------
// one block (256 threads) per (b,d) series.
__global__ void __launch_bounds__(256) k_fused(const float* __restrict__ W_trend,
                                               const float* __restrict__ b_trend,
                                               const float* __restrict__ W_lin) {
    __shared__ float s_re[2][512];
    __shared__ float s_im[2][512];
    __shared__ float s_cos[512];          // cospi(j/256) = cos(2*pi*j/512)
    __shared__ float s_sin[512];          // sinpi(j/256)
    __shared__ float s_x[512];
    __shared__ float s_rem[512];
    __shared__ float s_cs[513];
    __shared__ float s_wA[8];             // cross-warp argmax scratch
    __shared__ int   s_wK[8];
    __shared__ int   s_win;
    __shared__ int   win_k[4];
    __shared__ float win_r[4], win_i[4];
    __shared__ float s_red[8];

    int gid = blockIdx.x;                 // b*512 + d
    int tid = threadIdx.x;
    int lane = tid & 31, w = tid >> 5;

    // trig table: 2 sincospif per thread
    {
        float s0, c0, s1, c1;
        sincospif((float)tid * (1.0f / 256.0f), &s0, &c0);
        sincospif((float)(tid + 256) * (1.0f / 256.0f), &s1, &c1);
        s_cos[tid] = c0; s_sin[tid] = s0;
        s_cos[tid + 256] = c1; s_sin[tid + 256] = s1;
    }
    // load series
    const float* xs = g_xT + (size_t)gid * TT;
    float x0 = xs[tid], x1 = xs[tid + 256];
    s_x[tid] = x0; s_x[tid + 256] = x1;
    s_re[0][tid] = x0; s_re[0][tid + 256] = x1;
    s_im[0][tid] = 0.f; s_im[0][tid + 256] = 0.f;

    // ---- Stockham radix-2 FFT, 9 stages, forward (e^{-i 2 pi k t / N}) ----
    int cur = 0;
    #pragma unroll
    for (int s = 0; s < 9; s++) {
        __syncthreads();
        int Ns = 1 << s;
        int k  = tid & (Ns - 1);
        int grp = tid >> s;
        int idx = k << (8 - s);           // twiddle angle pi*idx/256 = pi*k/Ns
        float wr = s_cos[idx], wi = -s_sin[idx];
        float ar = s_re[cur][tid],       ai = s_im[cur][tid];
        float br = s_re[cur][tid + 256], bi = s_im[cur][tid + 256];
        float tr = wr * br - wi * bi;
        float ti = wr * bi + wi * br;
        int o = (grp << (s + 1)) + k;
        int nxt = cur ^ 1;
        s_re[nxt][o]      = ar + tr; s_im[nxt][o]      = ai + ti;
        s_re[nxt][o + Ns] = ar - tr; s_im[nxt][o + Ns] = ai - ti;
        cur = nxt;
    }
    __syncthreads();

    // my spectrum element: k = tid (valid 1..255)
    float fr = s_re[cur][tid], fi = s_im[cur][tid];
    float myAmp = (tid >= 1 && tid <= 255) ? (fr * fr + fi * fi) : -3.f;

    // ---- top-4 via 4 argmax reductions (amp desc, k asc) ----
    #pragma unroll
    for (int r = 0; r < 4; r++) {
        float a = myAmp; int kk = tid;
        #pragma unroll
        for (int o = 16; o > 0; o >>= 1) {
            float oa = __shfl_down_sync(0xffffffffu, a, o);
            int   ok = __shfl_down_sync(0xffffffffu, kk, o);
            if (oa > a || (oa == a && ok < kk)) { a = oa; kk = ok; }
        }
        if (lane == 0) { s_wA[w] = a; s_wK[w] = kk; }
        __syncthreads();
        if (tid == 0) {
            float ba = s_wA[0]; int bk = s_wK[0];
            #pragma unroll
            for (int ww = 1; ww < 8; ww++) {
                float oa = s_wA[ww]; int ok = s_wK[ww];
                if (oa > ba || (oa == ba && ok < bk)) { ba = oa; bk = ok; }
            }
            s_win = bk;
        }
        __syncthreads();
        if (tid == s_win) {
            win_k[r] = tid; win_r[r] = fr; win_i[r] = fi;
            myAmp = -2.f;
        }
        __syncthreads();
    }

    // ---- season + remainder: se = (2/T) * sum_j [ xr*cos(2pi k t/T) - xi*sin(...) ] ----
    int skk[4]; float sxr[4], sxi[4];
    #pragma unroll
    for (int j = 0; j < 4; j++) { skk[j] = win_k[j]; sxr[j] = win_r[j]; sxi[j] = win_i[j]; }
    #pragma unroll
    for (int tt = 0; tt < 2; tt++) {
        int t = tid + tt * 256;
        float se = 0.f;
        #pragma unroll
        for (int j = 0; j < 4; j++) {
            int idx = (skk[j] * t) & 511;
            se += sxr[j] * s_cos[idx] - sxi[j] * s_sin[idx];
        }
        se *= (2.0f / 512.0f);
        s_rem[t] = s_x[t] - se;
    }
    __syncthreads();

    // exclusive cumsum of rem into s_cs[0..512], warp 0 only
    if (tid < 32) {
        int base = tid * 16;
        float run = 0.f, pref[16];
        #pragma unroll
        for (int i = 0; i < 16; i++) { pref[i] = run; run += s_rem[base + i]; }
        float inc = run;
        #pragma unroll
        for (int sft = 1; sft < 32; sft <<= 1) {
            float v = __shfl_up_sync(0xffffffffu, inc, sft);
            if (tid >= sft) inc += v;
        }
        float excl = inc - run;
        #pragma unroll
        for (int i = 0; i < 16; i++) s_cs[base + i] = excl + pref[i];
        if (tid == 31) s_cs[512] = inc;
    }
    __syncthreads();

    float Wt[6], bt[6];
    #pragma unroll
    for (int j = 0; j < 6; j++) { Wt[j] = W_trend[j]; bt[j] = b_trend[j]; }
    const int   KSv[6] = {4, 8, 12, 16, 24, 32};
    const float inv[6] = {0.25f, 0.125f, 1.f / 12.f, 0.0625f, 1.f / 24.f, 0.03125f};
    float rem0 = s_rem[0], remL = s_rem[511];
    float acc = 0.f;

    #pragma unroll
    for (int tt = 0; tt < 2; tt++) {
        int t = tid + tt * 256;
        float rem = s_rem[t];
        float mm[6], lg[6];
        float mx = -FLT_MAX;
        #pragma unroll
        for (int j = 0; j < 6; j++) {
            int k = KSv[j];
            int front = k >> 1, end = (k >> 1) - 1;   // all KS even
            int lo = t - front, hi = t + end;
            int clo = lo < 0 ? 0 : lo;
            int chi = hi > 511 ? 511 : hi;
            float ssum = s_cs[chi + 1] - s_cs[clo];
            if (lo < 0)   ssum += (float)(-lo) * rem0;
            if (hi > 511) ssum += (float)(hi - 511) * remL;
            mm[j] = ssum * inv[j];
            float l = fmaf(rem, Wt[j], bt[j]);
            lg[j] = l;
            mx = fmaxf(mx, l);
        }
        float es = 0.f, ws = 0.f;
        #pragma unroll
        for (int j = 0; j < 6; j++) {
            float e = expf(lg[j] - mx);
            es += e;
            ws = fmaf(e, mm[j], ws);
        }
        float trend = ws / es;
        float xsum = 2.0f * s_x[t] - rem + trend;   // x + season + trend
        acc = fmaf(xsum, W_lin[t], acc);
    }

    #pragma unroll
    for (int o = 16; o > 0; o >>= 1) acc += __shfl_down_sync(0xffffffffu, acc, o);
    if (lane == 0) s_red[w] = acc;
    __syncthreads();
    if (tid == 0) {
        float s = 0.f;
        #pragma unroll
        for (int ww = 0; ww < 8; ww++) s += s_red[ww];
        g_xtr[gid] = s;
    }
}

// ---------------- final routing: (B,D)->(B,8), softplus noise, softmax, top-4 ----------------
__global__ void k_router(const float* __restrict__ noise, const float* __restrict__ W_r,
                         const float* __restrict__ b_r, const float* __restrict__ W_noise,
                         const float* __restrict__ b_noise, const float* __restrict__ b_lin,
                         float* __restrict__ out) {
    int b = blockIdx.x;
    int tid = threadIdx.x;
    int m = tid & 7, c = tid >> 3;   // c: 0..31 chunks of 16 d
    __shared__ float sp[256], sn[256];
    __shared__ float slog[8];
    const float* xt = g_xtr + b * DD;
    float blin = b_lin[0];
    float p = 0.f, pn = 0.f;
    #pragma unroll
    for (int i = 0; i < 16; i++) {
        int d = c * 16 + i;
        float v = xt[d] + blin;
        p  = fmaf(v, W_r[d * 8 + m], p);
        pn = fmaf(v, W_noise[d * 8 + m], pn);
    }
    sp[tid] = p; sn[tid] = pn;
    __syncthreads();
    if (tid < 8) {
        float P = 0.f, N = 0.f;
        for (int cc = 0; cc < 32; cc++) { P += sp[cc * 8 + tid]; N += sn[cc * 8 + tid]; }
        float base = P + b_r[tid];
        float nl = N + b_noise[tid];
        float ns = log1pf(expf(-fabsf(nl))) + fmaxf(nl, 0.f);   // softplus
        slog[tid] = base + noise[b * 8 + tid] * ns;
    }
    __syncthreads();
    if (tid == 0) {
        float lg[8], mx = -FLT_MAX;
        #pragma unroll
        for (int i = 0; i < 8; i++) { lg[i] = slog[i]; mx = fmaxf(mx, lg[i]); }
        float es = 0.f, pw[8];
        #pragma unroll
        for (int i = 0; i < 8; i++) { pw[i] = expf(lg[i] - mx); es += pw[i]; }
        #pragma unroll
        for (int i = 0; i < 8; i++) pw[i] /= es;
        #pragma unroll
        for (int i = 0; i < 8; i++) {
            int rank = 0;
            #pragma unroll
            for (int j = 0; j < 8; j++)
                if (pw[j] > pw[i] || (pw[j] == pw[i] && j < i)) rank++;
            out[b * 8 + i] = (rank < 4) ? pw[i] : 0.f;
        }
    }
}

// ---------------- launch ----------------
extern "C" void kernel_launch(void* const* d_in, const int* in_sizes, int n_in,
                              void* d_out, int out_size) {
    const float* x       = (const float*)d_in[0];
    const float* noise   = (const float*)d_in[1];
    const float* W_r     = (const float*)d_in[2];
    const float* b_r     = (const float*)d_in[3];
    const float* W_noise = (const float*)d_in[4];
    const float* b_noise = (const float*)d_in[5];
    const float* W_trend = (const float*)d_in[6];
    const float* b_trend = (const float*)d_in[7];
    const float* W_lin   = (const float*)d_in[8];
    const float* b_lin   = (const float*)d_in[9];
    float* out = (float*)d_out;

    k_transpose<<<dim3(16, 16, 16), dim3(32, 8)>>>(x);
    k_fused<<<BB * DD, 256>>>(W_trend, b_trend, W_lin);
    k_router<<<16, 256>>>(noise, W_r, b_r, W_noise, b_noise, b_lin, out);
}

// round 5
// speedup vs baseline: 3.4972x; 1.5371x over previous
#include <cuda_runtime.h>
#include <math.h>
#include <float.h>

#define BB 16
#define TT 512
#define DD 512

typedef unsigned long long ull;
__device__ __forceinline__ ull umax64(ull a, ull b) { return a > b ? a : b; }
__device__ __forceinline__ ull umin64(ull a, ull b) { return a < b ? a : b; }

// ---------------- scratch (static __device__ — no allocations) ----------------
__device__ float g_xT[(size_t)BB * DD * TT];        // x transposed to [b][d][t]
__device__ float g_xtr[BB * DD];                    // x_trans (before +b_lin)

// ---------------- transpose x (B,T,D) -> (B,D,T) ----------------
__global__ void k_transpose(const float* __restrict__ x) {
    __shared__ float tile[32][33];
    int b  = blockIdx.z;
    int d0 = blockIdx.x * 32;
    int t0 = blockIdx.y * 32;
    int tx = threadIdx.x, ty = threadIdx.y;
    const float* xb = x + (size_t)b * TT * DD;
    #pragma unroll
    for (int i = ty; i < 32; i += 8)
        tile[i][tx] = xb[(size_t)(t0 + i) * DD + d0 + tx];
    __syncthreads();
    float* ob = g_xT + (size_t)b * DD * TT;
    #pragma unroll
    for (int i = ty; i < 32; i += 8)
        ob[(size_t)(d0 + i) * TT + t0 + tx] = tile[tx][i];
}

// ---------------- fused: 2 series per block via packed real FFT ----------------
__global__ void __launch_bounds__(256) k_fused(const float* __restrict__ W_trend,
                                               const float* __restrict__ b_trend,
                                               const float* __restrict__ W_lin) {
    __shared__ float s_re[2][512];
    __shared__ float s_im[2][512];
    __shared__ float s_cos[512];
    __shared__ float s_sin[512];
    __shared__ float s_xa[512], s_xb[512];
    __shared__ float s_amp[2][256];
    __shared__ float s_csA[513], s_csB[513];
    __shared__ int   s_wk[2][4];
    __shared__ float s_wr[2][4], s_wi[2][4];
    __shared__ float s_redA[8], s_redB[8];

    int gid0 = blockIdx.x * 2;
    int gid1 = gid0 + 1;
    int tid = threadIdx.x;
    int lane = tid & 31, w = tid >> 5;

    // trig table
    {
        float s0, c0, s1, c1;
        sincospif((float)tid * (1.0f / 256.0f), &s0, &c0);
        sincospif((float)(tid + 256) * (1.0f / 256.0f), &s1, &c1);
        s_cos[tid] = c0; s_sin[tid] = s0;
        s_cos[tid + 256] = c1; s_sin[tid + 256] = s1;
    }
    // load two series, pack z = xa + i*xb
    const float* ra = g_xT + (size_t)gid0 * TT;
    const float* rb = g_xT + (size_t)gid1 * TT;
    float xa0 = ra[tid], xa1 = ra[tid + 256];
    float xb0 = rb[tid], xb1 = rb[tid + 256];
    s_xa[tid] = xa0; s_xa[tid + 256] = xa1;
    s_xb[tid] = xb0; s_xb[tid + 256] = xb1;
    s_re[0][tid] = xa0; s_re[0][tid + 256] = xa1;
    s_im[0][tid] = xb0; s_im[0][tid + 256] = xb1;

    // ---- Stockham radix-2 FFT, 9 stages, forward ----
    int cur = 0;
    #pragma unroll
    for (int s = 0; s < 9; s++) {
        __syncthreads();
        int Ns = 1 << s;
        int k  = tid & (Ns - 1);
        int grp = tid >> s;
        int idx = k << (8 - s);
        float wr = s_cos[idx], wi = -s_sin[idx];
        float ar = s_re[cur][tid],       ai = s_im[cur][tid];
        float br = s_re[cur][tid + 256], bi = s_im[cur][tid + 256];
        float tr = wr * br - wi * bi;
        float ti = wr * bi + wi * br;
        int o = (grp << (s + 1)) + k;
        int nxt = cur ^ 1;
        s_re[nxt][o]      = ar + tr; s_im[nxt][o]      = ai + ti;
        s_re[nxt][o + Ns] = ar - tr; s_im[nxt][o + Ns] = ai - ti;
        cur = nxt;
    }
    __syncthreads();
    // spectrum now in buf 1 (cur==1). Unpack into buf 0:
    //   Xa_r->s_re[0][k], Xa_i->s_re[0][256+k], Xb_r->s_im[0][k], Xb_i->s_im[0][256+k]
    if (tid >= 1) {
        int k = tid, mk = 512 - tid;
        float Zr = s_re[1][k],  Zi = s_im[1][k];
        float Mr = s_re[1][mk], Mi = s_im[1][mk];
        float Xar = 0.5f * (Zr + Mr), Xai = 0.5f * (Zi - Mi);
        float Xbr = 0.5f * (Zi + Mi), Xbi = 0.5f * (Mr - Zr);
        s_re[0][k] = Xar; s_re[0][256 + k] = Xai;
        s_im[0][k] = Xbr; s_im[0][256 + k] = Xbi;
        s_amp[0][k] = Xar * Xar + Xai * Xai;
        s_amp[1][k] = Xbr * Xbr + Xbi * Xbi;
    } else {
        s_amp[0][0] = -1.f; s_amp[1][0] = -1.f;
    }
    __syncthreads();

    // ---- warp top-4: warp0 -> series A, warp1 -> series B ----
    // packed key: amp_bits<<32 | (511-k)  (amp desc, then k asc)
    if (w < 2) {
        const float* amp = s_amp[w];
        ull c0 = 0, c1 = 0, c2 = 0, c3 = 0;
        #pragma unroll
        for (int j = 0; j < 8; j++) {
            int k = lane + 32 * j;
            ull p = (k == 0) ? 0ull
                  : (((ull)__float_as_uint(amp[k]) << 32) | (ull)(511 - k));
            ull t;
            t = umin64(c0, p); c0 = umax64(c0, p); p = t;
            t = umin64(c1, p); c1 = umax64(c1, p); p = t;
            t = umin64(c2, p); c2 = umax64(c2, p); p = t;
            c3 = umax64(c3, p);
        }
        #pragma unroll
        for (int off = 16; off; off >>= 1) {
            ull o0 = __shfl_xor_sync(0xffffffffu, c0, off);
            ull o1 = __shfl_xor_sync(0xffffffffu, c1, off);
            ull o2 = __shfl_xor_sync(0xffffffffu, c2, off);
            ull o3 = __shfl_xor_sync(0xffffffffu, c3, off);
            bool mf = c0 > o0;                 // canonical order (keys distinct)
            ull u0 = mf ? c0 : o0, u1 = mf ? c1 : o1, u2 = mf ? c2 : o2, u3 = mf ? c3 : o3;
            ull v0 = mf ? o0 : c0, v1 = mf ? o1 : c1, v2 = mf ? o2 : c2, v3 = mf ? o3 : c3;
            ull A0 = umax64(u0, v3), A1 = umax64(u1, v2);
            ull A2 = umax64(u2, v1), A3 = umax64(u3, v0);
            ull B0 = umax64(A0, A2), B2 = umin64(A0, A2);
            ull B1 = umax64(A1, A3), B3 = umin64(A1, A3);
            c0 = umax64(B0, B1); c1 = umin64(B0, B1);
            c2 = umax64(B2, B3); c3 = umin64(B2, B3);
        }
        if (lane == 0) {
            const float* Xr = w ? s_im[0] : s_re[0];
            int k0 = 511 - (int)(c0 & 0xffffffffull);
            int k1 = 511 - (int)(c1 & 0xffffffffull);
            int k2 = 511 - (int)(c2 & 0xffffffffull);
            int k3 = 511 - (int)(c3 & 0xffffffffull);
            s_wk[w][0] = k0; s_wr[w][0] = Xr[k0]; s_wi[w][0] = Xr[256 + k0];
            s_wk[w][1] = k1; s_wr[w][1] = Xr[k1]; s_wi[w][1] = Xr[256 + k1];
            s_wk[w][2] = k2; s_wr[w][2] = Xr[k2]; s_wi[w][2] = Xr[256 + k2];
            s_wk[w][3] = k3; s_wr[w][3] = Xr[k3]; s_wi[w][3] = Xr[256 + k3];
        }
    }
    __syncthreads();

    // ---- season + remainder for both series; rem stored in buf1 (free now) ----
    int   kA[4], kB[4];
    float rA[4], iA[4], rB[4], iB[4];
    #pragma unroll
    for (int j = 0; j < 4; j++) {
        kA[j] = s_wk[0][j]; rA[j] = s_wr[0][j]; iA[j] = s_wi[0][j];
        kB[j] = s_wk[1][j]; rB[j] = s_wr[1][j]; iB[j] = s_wi[1][j];
    }
    #pragma unroll
    for (int tt = 0; tt < 2; tt++) {
        int t = tid + tt * 256;
        float seA = 0.f, seB = 0.f;
        #pragma unroll
        for (int j = 0; j < 4; j++) {
            int ia = (kA[j] * t) & 511;
            seA += rA[j] * s_cos[ia] - iA[j] * s_sin[ia];
            int ib = (kB[j] * t) & 511;
            seB += rB[j] * s_cos[ib] - iB[j] * s_sin[ib];
        }
        s_re[1][t] = s_xa[t] - seA * (2.0f / 512.0f);   // remA
        s_im[1][t] = s_xb[t] - seB * (2.0f / 512.0f);   // remB
    }
    __syncthreads();

    // ---- dual exclusive cumsum: warp0 -> csA over remA, warp1 -> csB over remB ----
    if (w < 2) {
        const float* rem = w ? s_im[1] : s_re[1];
        float* cs = w ? s_csB : s_csA;
        int base = lane * 16;
        float run = 0.f, pref[16];
        #pragma unroll
        for (int i = 0; i < 16; i++) { pref[i] = run; run += rem[base + i]; }
        float inc = run;
        #pragma unroll
        for (int sft = 1; sft < 32; sft <<= 1) {
            float v = __shfl_up_sync(0xffffffffu, inc, sft);
            if (lane >= sft) inc += v;
        }
        float excl = inc - run;
        #pragma unroll
        for (int i = 0; i < 16; i++) cs[base + i] = excl + pref[i];
        if (lane == 31) cs[512] = inc;
    }
    __syncthreads();

    // ---- trend + W_lin reduce, both series ----
    float Wt[6], bt[6];
    #pragma unroll
    for (int j = 0; j < 6; j++) { Wt[j] = W_trend[j]; bt[j] = b_trend[j]; }
    const int   KSv[6] = {4, 8, 12, 16, 24, 32};
    const float inv[6] = {0.25f, 0.125f, 1.f / 12.f, 0.0625f, 1.f / 24.f, 0.03125f};
    float wl0 = W_lin[tid], wl1 = W_lin[tid + 256];

    float accA = 0.f, accB = 0.f;
    #pragma unroll
    for (int srs = 0; srs < 2; srs++) {
        const float* rem_s = srs ? s_im[1] : s_re[1];
        const float* cs_s  = srs ? s_csB : s_csA;
        const float* x_s   = srs ? s_xb : s_xa;
        float rem0 = rem_s[0], remL = rem_s[511];
        float acc = 0.f;
        #pragma unroll
        for (int tt = 0; tt < 2; tt++) {
            int t = tid + tt * 256;
            float rem = rem_s[t];
            float mm[6], lg[6];
            float mx = -FLT_MAX;
            #pragma unroll
            for (int j = 0; j < 6; j++) {
                int k = KSv[j];
                int lo = t - (k >> 1), hi = t + (k >> 1) - 1;
                int clo = lo < 0 ? 0 : lo;
                int chi = hi > 511 ? 511 : hi;
                float ssum = cs_s[chi + 1] - cs_s[clo];
                if (lo < 0)   ssum += (float)(-lo) * rem0;
                if (hi > 511) ssum += (float)(hi - 511) * remL;
                mm[j] = ssum * inv[j];
                float l = fmaf(rem, Wt[j], bt[j]);
                lg[j] = l;
                mx = fmaxf(mx, l);
            }
            float es = 0.f, ws = 0.f;
            #pragma unroll
            for (int j = 0; j < 6; j++) {
                float e = __expf(lg[j] - mx);
                es += e;
                ws = fmaf(e, mm[j], ws);
            }
            float trend = ws / es;
            float xsum = 2.0f * x_s[t] - rem + trend;
            acc = fmaf(xsum, (tt ? wl1 : wl0), acc);
        }
        if (srs) accB = acc; else accA = acc;
    }

    #pragma unroll
    for (int o = 16; o > 0; o >>= 1) {
        accA += __shfl_down_sync(0xffffffffu, accA, o);
        accB += __shfl_down_sync(0xffffffffu, accB, o);
    }
    if (lane == 0) { s_redA[w] = accA; s_redB[w] = accB; }
    __syncthreads();
    if (tid == 0) {
        float sa = 0.f, sb = 0.f;
        #pragma unroll
        for (int ww = 0; ww < 8; ww++) { sa += s_redA[ww]; sb += s_redB[ww]; }
        g_xtr[gid0] = sa;
        g_xtr[gid1] = sb;
    }
}

// ---------------- final routing: (B,D)->(B,8), softplus noise, softmax, top-4 ----------------
__global__ void k_router(const float* __restrict__ noise, const float* __restrict__ W_r,
                         const float* __restrict__ b_r, const float* __restrict__ W_noise,
                         const float* __restrict__ b_noise, const float* __restrict__ b_lin,
                         float* __restrict__ out) {
    int b = blockIdx.x;
    int tid = threadIdx.x;
    int m = tid & 7, c = tid >> 3;
    __shared__ float sp[256], sn[256];
    __shared__ float slog[8];
    const float* xt = g_xtr + b * DD;
    float blin = b_lin[0];
    float p = 0.f, pn = 0.f;
    #pragma unroll
    for (int i = 0; i < 16; i++) {
        int d = c * 16 + i;
        float v = xt[d] + blin;
        p  = fmaf(v, W_r[d * 8 + m], p);
        pn = fmaf(v, W_noise[d * 8 + m], pn);
    }
    sp[tid] = p; sn[tid] = pn;
    __syncthreads();
    if (tid < 8) {
        float P = 0.f, N = 0.f;
        for (int cc = 0; cc < 32; cc++) { P += sp[cc * 8 + tid]; N += sn[cc * 8 + tid]; }
        float base = P + b_r[tid];
        float nl = N + b_noise[tid];
        float ns = log1pf(expf(-fabsf(nl))) + fmaxf(nl, 0.f);   // softplus (keep accurate)
        slog[tid] = base + noise[b * 8 + tid] * ns;
    }
    __syncthreads();
    if (tid == 0) {
        float lg[8], mx = -FLT_MAX;
        #pragma unroll
        for (int i = 0; i < 8; i++) { lg[i] = slog[i]; mx = fmaxf(mx, lg[i]); }
        float es = 0.f, pw[8];
        #pragma unroll
        for (int i = 0; i < 8; i++) { pw[i] = expf(lg[i] - mx); es += pw[i]; }
        #pragma unroll
        for (int i = 0; i < 8; i++) pw[i] /= es;
        #pragma unroll
        for (int i = 0; i < 8; i++) {
            int rank = 0;
            #pragma unroll
            for (int j = 0; j < 8; j++)
                if (pw[j] > pw[i] || (pw[j] == pw[i] && j < i)) rank++;
            out[b * 8 + i] = (rank < 4) ? pw[i] : 0.f;
        }
    }
}

// ---------------- launch ----------------
extern "C" void kernel_launch(void* const* d_in, const int* in_sizes, int n_in,
                              void* d_out, int out_size) {
    const float* x       = (const float*)d_in[0];
    const float* noise   = (const float*)d_in[1];
    const float* W_r     = (const float*)d_in[2];
    const float* b_r     = (const float*)d_in[3];
    const float* W_noise = (const float*)d_in[4];
    const float* b_noise = (const float*)d_in[5];
    const float* W_trend = (const float*)d_in[6];
    const float* b_trend = (const float*)d_in[7];
    const float* W_lin   = (const float*)d_in[8];
    const float* b_lin   = (const float*)d_in[9];
    float* out = (float*)d_out;

    k_transpose<<<dim3(16, 16, 16), dim3(32, 8)>>>(x);
    k_fused<<<BB * DD / 2, 256>>>(W_trend, b_trend, W_lin);
    k_router<<<16, 256>>>(noise, W_r, b_r, W_noise, b_noise, b_lin, out);
}

// round 7
// speedup vs baseline: 4.1529x; 1.1875x over previous
#include <cuda_runtime.h>
#include <math.h>
#include <float.h>

#define BB 16
#define TT 512
#define DD 512

typedef unsigned long long ull;
__device__ __forceinline__ ull umax64(ull a, ull b) { return a > b ? a : b; }
__device__ __forceinline__ ull umin64(ull a, ull b) { return a < b ? a : b; }

// ---------------- scratch (static __device__ — no allocations) ----------------
__device__ float g_xtr[BB * DD];                    // x_trans (before +b_lin)

// ---------------- fused: 4 series per block, 2 packed real FFTs (radix-4) ----------------
__global__ void __launch_bounds__(256) k_fused(const float* __restrict__ x,
                                               const float* __restrict__ W_trend,
                                               const float* __restrict__ b_trend,
                                               const float* __restrict__ W_lin) {
    __shared__ float s_re[2][1024];     // [pingpong][fft*512 + idx]
    __shared__ float s_im[2][1024];
    __shared__ float s_cos[512];
    __shared__ float s_sin[512];
    __shared__ float s_x[4][512];
    __shared__ float s_cs[4][513];
    __shared__ int   s_wk[4][4];
    __shared__ float s_wr[4][4], s_wi[4][4];
    __shared__ float s_red[4][8];

    int tid = threadIdx.x;
    int lane = tid & 31, w = tid >> 5;
    int bidx = blockIdx.x;
    int b  = bidx >> 7;                 // 128 blocks per batch (512/4)
    int d0 = (bidx & 127) << 2;

    // issue strided global loads first (latency hidden by trig below)
    const float* xp = x + ((size_t)b * TT + tid) * DD + d0;
    float4 v0 = *(const float4*)xp;
    float4 v1 = *(const float4*)(xp + (size_t)256 * DD);

    // trig table
    {
        float s0, c0, s1, c1;
        sincospif((float)tid * (1.0f / 256.0f), &s0, &c0);
        sincospif((float)(tid + 256) * (1.0f / 256.0f), &s1, &c1);
        s_cos[tid] = c0; s_sin[tid] = s0;
        s_cos[tid + 256] = c1; s_sin[tid + 256] = s1;
    }

    // stash x; pack fft0 = x(d0) + i x(d0+1), fft1 = x(d0+2) + i x(d0+3)
    s_x[0][tid] = v0.x; s_x[1][tid] = v0.y; s_x[2][tid] = v0.z; s_x[3][tid] = v0.w;
    s_x[0][tid + 256] = v1.x; s_x[1][tid + 256] = v1.y;
    s_x[2][tid + 256] = v1.z; s_x[3][tid + 256] = v1.w;
    s_re[0][tid]       = v0.x; s_im[0][tid]       = v0.y;
    s_re[0][tid + 256] = v1.x; s_im[0][tid + 256] = v1.y;
    s_re[0][512 + tid]       = v0.z; s_im[0][512 + tid]       = v0.w;
    s_re[0][512 + tid + 256] = v1.z; s_im[0][512 + tid + 256] = v1.w;

    // ---- 4 radix-4 Stockham stages (Ns = 1,4,16,64), 2 FFTs in parallel ----
    int cur = 0;
    #pragma unroll
    for (int st = 0; st < 4; st++) {
        int Ns = 1 << (2 * st);
        int shiftm = 7 - 2 * st;         // twiddle idx = k * (128/Ns)
        __syncthreads();
        int f = tid >> 7;                // fft id
        int j = tid & 127;
        int k = j & (Ns - 1);
        int base = f << 9;
        float x0r = s_re[cur][base + j],       x0i = s_im[cur][base + j];
        float x1r = s_re[cur][base + j + 128], x1i = s_im[cur][base + j + 128];
        float x2r = s_re[cur][base + j + 256], x2i = s_im[cur][base + j + 256];
        float x3r = s_re[cur][base + j + 384], x3i = s_im[cur][base + j + 384];
        int m = k << shiftm;
        float c1w = s_cos[m],     s1w = s_sin[m];
        float c2w = s_cos[2 * m], s2w = s_sin[2 * m];
        float c3w = s_cos[3 * m], s3w = s_sin[3 * m];
        // t = W*x, W = (c, -s)
        float t1r = c1w * x1r + s1w * x1i, t1i = c1w * x1i - s1w * x1r;
        float t2r = c2w * x2r + s2w * x2i, t2i = c2w * x2i - s2w * x2r;
        float t3r = c3w * x3r + s3w * x3i, t3i = c3w * x3i - s3w * x3r;
        float y0r = x0r + t1r + t2r + t3r, y0i = x0i + t1i + t2i + t3i;
        float y2r = x0r - t1r + t2r - t3r, y2i = x0i - t1i + t2i - t3i;
        float y1r = x0r + t1i - t2r - t3i, y1i = x0i - t1r - t2i + t3r;
        float y3r = x0r - t1i - t2r + t3i, y3i = x0i + t1r - t2i - t3r;
        int o = base + 4 * j - 3 * k;
        int nxt = cur ^ 1;
        s_re[nxt][o]          = y0r; s_im[nxt][o]          = y0i;
        s_re[nxt][o + Ns]     = y1r; s_im[nxt][o + Ns]     = y1i;
        s_re[nxt][o + 2 * Ns] = y2r; s_im[nxt][o + 2 * Ns] = y2i;
        s_re[nxt][o + 3 * Ns] = y3r; s_im[nxt][o + 3 * Ns] = y3i;
        cur = nxt;
    }
    // ---- final radix-2 stage (Ns = 256), each thread does both FFTs ----
    __syncthreads();
    {
        int k = tid;
        float cw = s_cos[k], sw = s_sin[k];
        int nxt = cur ^ 1;
        #pragma unroll
        for (int f = 0; f < 2; f++) {
            int base = f << 9;
            float ar = s_re[cur][base + k],       ai = s_im[cur][base + k];
            float br = s_re[cur][base + k + 256], bi = s_im[cur][base + k + 256];
            float tr = cw * br + sw * bi, ti = cw * bi - sw * br;
            s_re[nxt][base + k]       = ar + tr; s_im[nxt][base + k]       = ai + ti;
            s_re[nxt][base + k + 256] = ar - tr; s_im[nxt][base + k + 256] = ai - ti;
        }
        cur = nxt;                        // final spectrum in buf `cur` (==1)
    }
    __syncthreads();

    // ---- unpack: spectra of 4 series into buf0: Xr -> s_re[0][s*256+k], Xi -> s_im[0][s*256+k]
    if (tid >= 1) {
        int k = tid, mk = 512 - tid;
        #pragma unroll
        for (int f = 0; f < 2; f++) {
            int base = f << 9;
            float Zr = s_re[1][base + k],  Zi = s_im[1][base + k];
            float Mr = s_re[1][base + mk], Mi = s_im[1][base + mk];
            float Xar = 0.5f * (Zr + Mr), Xai = 0.5f * (Zi - Mi);
            float Xbr = 0.5f * (Zi + Mi), Xbi = 0.5f * (Mr - Zr);
            int sA = 2 * f, sB = 2 * f + 1;
            s_re[0][sA * 256 + k] = Xar; s_im[0][sA * 256 + k] = Xai;
            s_re[0][sB * 256 + k] = Xbr; s_im[0][sB * 256 + k] = Xbi;
        }
    }
    __syncthreads();

    // ---- warp top-4 per series (warps 0..3), key = amp_bits<<32 | (511-k) ----
    if (w < 4) {
        const float* Xr = &s_re[0][w * 256];
        const float* Xi = &s_im[0][w * 256];
        ull c0 = 0, c1 = 0, c2 = 0, c3 = 0;
        #pragma unroll
        for (int j = 0; j < 8; j++) {
            int k = lane + 32 * j;
            float xr = Xr[k], xi = Xi[k];
            float a = xr * xr + xi * xi;
            ull p = (k == 0) ? 0ull
                  : (((ull)__float_as_uint(a) << 32) | (ull)(511 - k));
            ull t;
            t = umin64(c0, p); c0 = umax64(c0, p); p = t;
            t = umin64(c1, p); c1 = umax64(c1, p); p = t;
            t = umin64(c2, p); c2 = umax64(c2, p); p = t;
            c3 = umax64(c3, p);
        }
        #pragma unroll
        for (int off = 16; off; off >>= 1) {
            ull o0 = __shfl_xor_sync(0xffffffffu, c0, off);
            ull o1 = __shfl_xor_sync(0xffffffffu, c1, off);
            ull o2 = __shfl_xor_sync(0xffffffffu, c2, off);
            ull o3 = __shfl_xor_sync(0xffffffffu, c3, off);
            bool mf = c0 > o0;
            ull u0 = mf ? c0 : o0, u1 = mf ? c1 : o1, u2 = mf ? c2 : o2, u3 = mf ? c3 : o3;
            ull v0 = mf ? o0 : c0, v1 = mf ? o1 : c1, v2 = mf ? o2 : c2, v3 = mf ? o3 : c3;
            ull A0 = umax64(u0, v3), A1 = umax64(u1, v2);
            ull A2 = umax64(u2, v1), A3 = umax64(u3, v0);
            ull B0 = umax64(A0, A2), B2 = umin64(A0, A2);
            ull B1 = umax64(A1, A3), B3 = umin64(A1, A3);
            c0 = umax64(B0, B1); c1 = umin64(B0, B1);
            c2 = umax64(B2, B3); c3 = umin64(B2, B3);
        }
        if (lane == 0) {
            int k0 = 511 - (int)(c0 & 0xffffffffull);
            int k1 = 511 - (int)(c1 & 0xffffffffull);
            int k2 = 511 - (int)(c2 & 0xffffffffull);
            int k3 = 511 - (int)(c3 & 0xffffffffull);
            s_wk[w][0] = k0; s_wr[w][0] = Xr[k0]; s_wi[w][0] = Xi[k0];
            s_wk[w][1] = k1; s_wr[w][1] = Xr[k1]; s_wi[w][1] = Xi[k1];
            s_wk[w][2] = k2; s_wr[w][2] = Xr[k2]; s_wi[w][2] = Xi[k2];
            s_wk[w][3] = k3; s_wr[w][3] = Xr[k3]; s_wi[w][3] = Xi[k3];
        }
    }
    __syncthreads();

    // rem layout in buf1 (spectrum no longer needed):
    //   s0 -> s_re[1][t], s1 -> s_re[1][512+t], s2 -> s_im[1][t], s3 -> s_im[1][512+t]
    // ---- season + remainder, per series sequential (register pressure) ----
    #pragma unroll
    for (int s = 0; s < 4; s++) {
        int   kk0 = s_wk[s][0], kk1 = s_wk[s][1], kk2 = s_wk[s][2], kk3 = s_wk[s][3];
        float r0 = s_wr[s][0], r1 = s_wr[s][1], r2 = s_wr[s][2], r3 = s_wr[s][3];
        float i0 = s_wi[s][0], i1 = s_wi[s][1], i2 = s_wi[s][2], i3 = s_wi[s][3];
        float* remp = (s & 2) ? &s_im[1][(s & 1) * 512] : &s_re[1][(s & 1) * 512];
        #pragma unroll
        for (int tt = 0; tt < 2; tt++) {
            int t = tid + tt * 256;
            int a0 = (kk0 * t) & 511, a1 = (kk1 * t) & 511;
            int a2 = (kk2 * t) & 511, a3 = (kk3 * t) & 511;
            float se = r0 * s_cos[a0] - i0 * s_sin[a0]
                     + r1 * s_cos[a1] - i1 * s_sin[a1]
                     + r2 * s_cos[a2] - i2 * s_sin[a2]
                     + r3 * s_cos[a3] - i3 * s_sin[a3];
            remp[t] = s_x[s][t] - se * (2.0f / 512.0f);
        }
    }
    __syncthreads();

    // ---- 4 parallel exclusive cumsums (warp w -> series w) ----
    if (w < 4) {
        const float* rm = (w & 2) ? &s_im[1][(w & 1) * 512] : &s_re[1][(w & 1) * 512];
        float* cs = s_cs[w];
        int base = lane * 16;
        float run = 0.f, pref[16];
        #pragma unroll
        for (int i = 0; i < 16; i++) { pref[i] = run; run += rm[base + i]; }
        float inc = run;
        #pragma unroll
        for (int sft = 1; sft < 32; sft <<= 1) {
            float v = __shfl_up_sync(0xffffffffu, inc, sft);
            if (lane >= sft) inc += v;
        }
        float excl = inc - run;
        #pragma unroll
        for (int i = 0; i < 16; i++) cs[base + i] = excl + pref[i];
        if (lane == 31) cs[512] = inc;
    }
    __syncthreads();

    // ---- trend + W_lin reduce, 4 series ----
    float Wt[6], bt[6];
    #pragma unroll
    for (int j = 0; j < 6; j++) { Wt[j] = W_trend[j]; bt[j] = b_trend[j]; }
    const int   KSv[6] = {4, 8, 12, 16, 24, 32};
    const float inv[6] = {0.25f, 0.125f, 1.f / 12.f, 0.0625f, 1.f / 24.f, 0.03125f};
    float wl0 = W_lin[tid], wl1 = W_lin[tid + 256];

    float accv[4];
    #pragma unroll
    for (int s = 0; s < 4; s++) {
        const float* rem_s = (s & 2) ? &s_im[1][(s & 1) * 512] : &s_re[1][(s & 1) * 512];
        const float* cs_s  = s_cs[s];
        const float* x_s   = s_x[s];
        float rem0 = rem_s[0], remL = rem_s[511];
        float acc = 0.f;
        #pragma unroll
        for (int tt = 0; tt < 2; tt++) {
            int t = tid + tt * 256;
            float rem = rem_s[t];
            float mm[6], lg[6];
            float mx = -FLT_MAX;
            #pragma unroll
            for (int j = 0; j < 6; j++) {
                int k = KSv[j];
                int lo = t - (k >> 1), hi = t + (k >> 1) - 1;
                int clo = lo < 0 ? 0 : lo;
                int chi = hi > 511 ? 511 : hi;
                float ssum = cs_s[chi + 1] - cs_s[clo];
                if (lo < 0)   ssum += (float)(-lo) * rem0;
                if (hi > 511) ssum += (float)(hi - 511) * remL;
                mm[j] = ssum * inv[j];
                float l = fmaf(rem, Wt[j], bt[j]);
                lg[j] = l;
                mx = fmaxf(mx, l);
            }
            float es = 0.f, ws = 0.f;
            #pragma unroll
            for (int j = 0; j < 6; j++) {
                float e = __expf(lg[j] - mx);
                es += e;
                ws = fmaf(e, mm[j], ws);
            }
            float trend = ws / es;
            float xsum = 2.0f * x_s[t] - rem + trend;
            acc = fmaf(xsum, (tt ? wl1 : wl0), acc);
        }
        accv[s] = acc;
    }

    #pragma unroll
    for (int o = 16; o > 0; o >>= 1) {
        accv[0] += __shfl_down_sync(0xffffffffu, accv[0], o);
        accv[1] += __shfl_down_sync(0xffffffffu, accv[1], o);
        accv[2] += __shfl_down_sync(0xffffffffu, accv[2], o);
        accv[3] += __shfl_down_sync(0xffffffffu, accv[3], o);
    }
    if (lane == 0) {
        s_red[0][w] = accv[0]; s_red[1][w] = accv[1];
        s_red[2][w] = accv[2]; s_red[3][w] = accv[3];
    }
    __syncthreads();
    if (tid < 4) {
        float s = 0.f;
        #pragma unroll
        for (int ww = 0; ww < 8; ww++) s += s_red[tid][ww];
        g_xtr[blockIdx.x * 4 + tid] = s;
    }
}

// ---------------- final routing: (B,D)->(B,8), softplus noise, softmax, top-4 ----------------
__global__ void k_router(const float* __restrict__ noise, const float* __restrict__ W_r,
                         const float* __restrict__ b_r, const float* __restrict__ W_noise,
                         const float* __restrict__ b_noise, const float* __restrict__ b_lin,
                         float* __restrict__ out) {
    int b = blockIdx.x;
    int tid = threadIdx.x;
    int m = tid & 7, c = tid >> 3;
    __shared__ float sp[256], sn[256];
    __shared__ float slog[8];
    const float* xt = g_xtr + b * DD;
    float blin = b_lin[0];
    float p = 0.f, pn = 0.f;
    #pragma unroll
    for (int i = 0; i < 16; i++) {
        int d = c * 16 + i;
        float v = xt[d] + blin;
        p  = fmaf(v, W_r[d * 8 + m], p);
        pn = fmaf(v, W_noise[d * 8 + m], pn);
    }
    sp[tid] = p; sn[tid] = pn;
    __syncthreads();
    if (tid < 8) {
        float P = 0.f, N = 0.f;
        for (int cc = 0; cc < 32; cc++) { P += sp[cc * 8 + tid]; N += sn[cc * 8 + tid]; }
        float base = P + b_r[tid];
        float nl = N + b_noise[tid];
        float ns = log1pf(expf(-fabsf(nl))) + fmaxf(nl, 0.f);   // softplus
        slog[tid] = base + noise[b * 8 + tid] * ns;
    }
    __syncthreads();
    if (tid == 0) {
        float lg[8], mx = -FLT_MAX;
        #pragma unroll
        for (int i = 0; i < 8; i++) { lg[i] = slog[i]; mx = fmaxf(mx, lg[i]); }
        float es = 0.f, pw[8];
        #pragma unroll
        for (int i = 0; i < 8; i++) { pw[i] = expf(lg[i] - mx); es += pw[i]; }
        #pragma unroll
        for (int i = 0; i < 8; i++) pw[i] /= es;
        #pragma unroll
        for (int i = 0; i < 8; i++) {
            int rank = 0;
            #pragma unroll
            for (int j = 0; j < 8; j++)
                if (pw[j] > pw[i] || (pw[j] == pw[i] && j < i)) rank++;
            out[b * 8 + i] = (rank < 4) ? pw[i] : 0.f;
        }
    }
}

// ---------------- launch ----------------
extern "C" void kernel_launch(void* const* d_in, const int* in_sizes, int n_in,
                              void* d_out, int out_size) {
    const float* x       = (const float*)d_in[0];
    const float* noise   = (const float*)d_in[1];
    const float* W_r     = (const float*)d_in[2];
    const float* b_r     = (const float*)d_in[3];
    const float* W_noise = (const float*)d_in[4];
    const float* b_noise = (const float*)d_in[5];
    const float* W_trend = (const float*)d_in[6];
    const float* b_trend = (const float*)d_in[7];
    const float* W_lin   = (const float*)d_in[8];
    const float* b_lin   = (const float*)d_in[9];
    float* out = (float*)d_out;

    k_fused<<<BB * DD / 4, 256>>>(x, W_trend, b_trend, W_lin);
    k_router<<<16, 256>>>(noise, W_r, b_r, W_noise, b_noise, b_lin, out);
}